// round 1
// baseline (speedup 1.0000x reference)
#include <cuda_runtime.h>
#include <math.h>

// Multi-head causal attention, fp32.
// q,k,v: [B,S,E] with E = H*D (head h occupies cols h*D..h*D+63)
// out:   [B,S,E]
// attn:  [B,H,S,S] (written only if the output buffer is large enough)

namespace {
constexpr int kB = 2, kS = 2048, kH = 16, kD = 64, kE = 1024;
constexpr int TQ = 64, TK = 64;
constexpr int NKT = kS / TK;          // 32 key tiles
constexpr float kScale = 0.125f;      // 1/sqrt(64)
constexpr int KVS = 68;               // smem stride for K^T / V tiles (16B-aligned, conflict-free)
constexpr int SMEM_FLOATS = 64 * 64   /* Qs */
                          + 64 * 64   /* Ps */
                          + 64 * KVS; /* KV  */
constexpr long long OUT_ELEMS  = (long long)kB * kS * kE;       // 4,194,304
constexpr long long ATTN_ELEMS = (long long)kB * kH * kS * kS;  // 134,217,728
}  // namespace

__global__ __launch_bounds__(256)
void attn_causal_kernel(const float* __restrict__ q,
                        const float* __restrict__ k,
                        const float* __restrict__ v,
                        float* __restrict__ out,
                        float* __restrict__ attn) {
    extern __shared__ float sm[];
    float* Qs = sm;                // [64][64]   Q tile (row-major, d contiguous)
    float* Ps = sm + 64 * 64;      // [64][64]   probability tile for PV GEMM
    float* KV = sm + 2 * 64 * 64;  // [64][KVS]  K tile transposed (Kt[d][c]) / V tile natural (V[k][d])
    __shared__ float mrow[64];
    __shared__ float lrow[64];

    const int tid = threadIdx.x;
    const int tx = tid & 15;       // 0..15 -> 4 columns each
    const int ty = tid >> 4;       // 0..15 -> 4 rows each
    const int r0 = ty * 4;
    const int c0 = tx * 4;

    const int qt = blockIdx.x;     // q tile index, 0..31
    const int bh = blockIdx.y;     // b*H + h, 0..31
    const int b  = bh >> 4;
    const int h  = bh & 15;

    const float* qbase = q + (long long)b * kS * kE + h * kD;
    const float* kbase = k + (long long)b * kS * kE + h * kD;
    const float* vbase = v + (long long)b * kS * kE + h * kD;
    float*       obase = out + (long long)b * kS * kE + h * kD;
    float*       abase = attn ? attn + (long long)bh * kS * kS : nullptr;

    // ---- load Q tile ----
    #pragma unroll
    for (int i = 0; i < 16; i++) {
        int e = tid + i * 256;        // 0..4095
        int r = e >> 6, d = e & 63;
        Qs[r * 64 + d] = qbase[(long long)(qt * 64 + r) * kE + d];
    }
    if (tid < 64) { mrow[tid] = -INFINITY; lrow[tid] = 0.f; }
    __syncthreads();

    // =========================================================
    // Phase 1: streaming row max (m) and sum-exp (l) over valid K tiles
    // =========================================================
    for (int kt = 0; kt <= qt; kt++) {
        // load K tile TRANSPOSED: KV[d][kr]
        #pragma unroll
        for (int i = 0; i < 16; i++) {
            int e = tid + i * 256;
            int kr = e >> 6, d = e & 63;
            KV[d * KVS + kr] = kbase[(long long)(kt * 64 + kr) * kE + d];
        }
        __syncthreads();

        // S = Q * K^T  (4x4 per thread)
        float acc[4][4] = {};
        #pragma unroll
        for (int d4 = 0; d4 < 64; d4 += 4) {
            float4 kv0 = *(const float4*)&KV[(d4 + 0) * KVS + c0];
            float4 kv1 = *(const float4*)&KV[(d4 + 1) * KVS + c0];
            float4 kv2 = *(const float4*)&KV[(d4 + 2) * KVS + c0];
            float4 kv3 = *(const float4*)&KV[(d4 + 3) * KVS + c0];
            #pragma unroll
            for (int i = 0; i < 4; i++) {
                float4 qv = *(const float4*)&Qs[(r0 + i) * 64 + d4];
                acc[i][0] += qv.x * kv0.x + qv.y * kv1.x + qv.z * kv2.x + qv.w * kv3.x;
                acc[i][1] += qv.x * kv0.y + qv.y * kv1.y + qv.z * kv2.y + qv.w * kv3.y;
                acc[i][2] += qv.x * kv0.z + qv.y * kv1.z + qv.z * kv2.z + qv.w * kv3.z;
                acc[i][3] += qv.x * kv0.w + qv.y * kv1.w + qv.z * kv2.w + qv.w * kv3.w;
            }
        }

        // scale + causal mask
        const int rq0 = qt * 64 + r0;
        const int ck0 = kt * 64 + c0;
        #pragma unroll
        for (int i = 0; i < 4; i++)
            #pragma unroll
            for (int j = 0; j < 4; j++) {
                float s = acc[i][j] * kScale;
                if (ck0 + j > rq0 + i) s = -INFINITY;
                acc[i][j] = s;
            }

        // row reductions across the 16 lanes owning this row group
        float mo[4], mn[4], se[4];
        #pragma unroll
        for (int i = 0; i < 4; i++) {
            float rm = fmaxf(fmaxf(acc[i][0], acc[i][1]), fmaxf(acc[i][2], acc[i][3]));
            #pragma unroll
            for (int off = 8; off > 0; off >>= 1)
                rm = fmaxf(rm, __shfl_xor_sync(0xffffffffu, rm, off, 16));
            mo[i] = mrow[r0 + i];
            mn[i] = fmaxf(mo[i], rm);
            float s = __expf(acc[i][0] - mn[i]) + __expf(acc[i][1] - mn[i]) +
                      __expf(acc[i][2] - mn[i]) + __expf(acc[i][3] - mn[i]);
            #pragma unroll
            for (int off = 8; off > 0; off >>= 1)
                s += __shfl_xor_sync(0xffffffffu, s, off, 16);
            se[i] = s;
        }
        __syncthreads();  // all mrow reads + KV reads done
        if (tx == 0) {
            #pragma unroll
            for (int i = 0; i < 4; i++) {
                lrow[r0 + i] = lrow[r0 + i] * __expf(mo[i] - mn[i]) + se[i];
                mrow[r0 + i] = mn[i];
            }
        }
    }
    __syncthreads();

    float mfin[4], lfin[4];
    #pragma unroll
    for (int i = 0; i < 4; i++) {
        mfin[i] = mrow[r0 + i];
        lfin[i] = 1.0f / lrow[r0 + i];
    }

    // =========================================================
    // Phase 2: recompute S, write normalized probs, accumulate O = P*V
    // =========================================================
    float oacc[4][4] = {};
    for (int kt = 0; kt <= qt; kt++) {
        #pragma unroll
        for (int i = 0; i < 16; i++) {
            int e = tid + i * 256;
            int kr = e >> 6, d = e & 63;
            KV[d * KVS + kr] = kbase[(long long)(kt * 64 + kr) * kE + d];
        }
        __syncthreads();

        float acc[4][4] = {};
        #pragma unroll
        for (int d4 = 0; d4 < 64; d4 += 4) {
            float4 kv0 = *(const float4*)&KV[(d4 + 0) * KVS + c0];
            float4 kv1 = *(const float4*)&KV[(d4 + 1) * KVS + c0];
            float4 kv2 = *(const float4*)&KV[(d4 + 2) * KVS + c0];
            float4 kv3 = *(const float4*)&KV[(d4 + 3) * KVS + c0];
            #pragma unroll
            for (int i = 0; i < 4; i++) {
                float4 qv = *(const float4*)&Qs[(r0 + i) * 64 + d4];
                acc[i][0] += qv.x * kv0.x + qv.y * kv1.x + qv.z * kv2.x + qv.w * kv3.x;
                acc[i][1] += qv.x * kv0.y + qv.y * kv1.y + qv.z * kv2.y + qv.w * kv3.y;
                acc[i][2] += qv.x * kv0.z + qv.y * kv1.z + qv.z * kv2.z + qv.w * kv3.z;
                acc[i][3] += qv.x * kv0.w + qv.y * kv1.w + qv.z * kv2.w + qv.w * kv3.w;
            }
        }

        const int rq0 = qt * 64 + r0;
        const int ck0 = kt * 64 + c0;
        float p[4][4];
        #pragma unroll
        for (int i = 0; i < 4; i++)
            #pragma unroll
            for (int j = 0; j < 4; j++) {
                bool valid = (ck0 + j) <= (rq0 + i);
                p[i][j] = valid ? __expf(acc[i][j] * kScale - mfin[i]) * lfin[i] : 0.0f;
            }

        // write attention probabilities
        if (abase) {
            #pragma unroll
            for (int i = 0; i < 4; i++) {
                float4 pv = make_float4(p[i][0], p[i][1], p[i][2], p[i][3]);
                *(float4*)&abase[(long long)(qt * 64 + r0 + i) * kS + kt * 64 + c0] = pv;
            }
        }
        __syncthreads();  // everyone done reading KV (K tile)

        // stage P into smem; load V tile (natural layout) into KV
        #pragma unroll
        for (int i = 0; i < 4; i++)
            *(float4*)&Ps[(r0 + i) * 64 + c0] = make_float4(p[i][0], p[i][1], p[i][2], p[i][3]);
        #pragma unroll
        for (int i = 0; i < 16; i++) {
            int e = tid + i * 256;
            int kr = e >> 6, d = e & 63;
            KV[kr * KVS + d] = vbase[(long long)(kt * 64 + kr) * kE + d];
        }
        __syncthreads();

        // O += P * V
        #pragma unroll
        for (int k4 = 0; k4 < 64; k4 += 4) {
            float4 vv0 = *(const float4*)&KV[(k4 + 0) * KVS + c0];
            float4 vv1 = *(const float4*)&KV[(k4 + 1) * KVS + c0];
            float4 vv2 = *(const float4*)&KV[(k4 + 2) * KVS + c0];
            float4 vv3 = *(const float4*)&KV[(k4 + 3) * KVS + c0];
            #pragma unroll
            for (int i = 0; i < 4; i++) {
                float4 pv = *(const float4*)&Ps[(r0 + i) * 64 + k4];
                oacc[i][0] += pv.x * vv0.x + pv.y * vv1.x + pv.z * vv2.x + pv.w * vv3.x;
                oacc[i][1] += pv.x * vv0.y + pv.y * vv1.y + pv.z * vv2.y + pv.w * vv3.y;
                oacc[i][2] += pv.x * vv0.z + pv.y * vv1.z + pv.z * vv2.z + pv.w * vv3.z;
                oacc[i][3] += pv.x * vv0.w + pv.y * vv1.w + pv.z * vv2.w + pv.w * vv3.w;
            }
        }
        __syncthreads();  // before next K tile overwrite
    }

    // write output tile
    #pragma unroll
    for (int i = 0; i < 4; i++) {
        float4 ov = make_float4(oacc[i][0], oacc[i][1], oacc[i][2], oacc[i][3]);
        *(float4*)&obase[(long long)(qt * 64 + r0 + i) * kE + c0] = ov;
    }

    // zero-fill masked (upper triangular) attention tiles
    if (abase) {
        const float4 z4 = make_float4(0.f, 0.f, 0.f, 0.f);
        for (int kt = qt + 1; kt < NKT; kt++) {
            #pragma unroll
            for (int i = 0; i < 4; i++) {
                int e4 = tid + i * 256;      // 0..1023 float4s
                int r  = e4 >> 4;            // 16 float4 per row
                int c4 = e4 & 15;
                *(float4*)&abase[(long long)(qt * 64 + r) * kS + kt * 64 + c4 * 4] = z4;
            }
        }
    }
}

extern "C" void kernel_launch(void* const* d_in, const int* in_sizes, int n_in,
                              void* d_out, int out_size) {
    const float* q = (const float*)d_in[0];
    const float* k = (const float*)d_in[1];
    const float* v = (const float*)d_in[2];
    // d_in[3] is the causal mask (deterministic tril) — applied analytically.
    float* out = (float*)d_out;

    float* attn = nullptr;
    if ((long long)out_size >= OUT_ELEMS + ATTN_ELEMS) {
        attn = out + OUT_ELEMS;  // tuple order: (out, attn)
    }

    const int smem_bytes = SMEM_FLOATS * (int)sizeof(float);  // 50176
    cudaFuncSetAttribute(attn_causal_kernel,
                         cudaFuncAttributeMaxDynamicSharedMemorySize, smem_bytes);

    dim3 grid(NKT, kB * kH);  // (q tiles, batch*heads)
    attn_causal_kernel<<<grid, 256, smem_bytes>>>(q, k, v, out, attn);
}